// round 6
// baseline (speedup 1.0000x reference)
#include <cuda_runtime.h>
#include <cstdint>
#include <mma.h>
#include <math.h>

using namespace nvcuda;

#define H        128
#define BM       64       // rows per tile (double-buffered)
#define XLD      132      // padded leading dim (floats)
#define NTHREADS 256      // 8 warps
#define NSM      152
#define SMEM_BYTES (2 * BM * XLD * 4)

// ---------------- scratch ----------------
#define MAX_NODES 100000
__device__ int   g_is64;
__device__ float g_A_src[(size_t)MAX_NODES * H];
__device__ float g_A_dst[(size_t)MAX_NODES * H];
// tf32-rounded weights: [0]=Wp [1]=Wc [2]=W1p [3]=W1c [4]=W1d [5]=W2, each 128x128 row-major (j*H+k)
__device__ float g_Wt[6 * H * H];

// ---------------- int32/int64 detection (parallel) ----------------
__global__ void detect_idx_kernel(const int* __restrict__ ei)
{
    int odd = ei[threadIdx.x * 2 + 1];
    unsigned any = __ballot_sync(0xFFFFFFFFu, odd != 0);
    __shared__ unsigned s[2];
    if ((threadIdx.x & 31) == 0) s[threadIdx.x >> 5] = any;
    __syncthreads();
    if (threadIdx.x == 0) g_is64 = (s[0] | s[1]) ? 0 : 1;
}

// ---------------- weight tf32 pre-round ----------------
__global__ void convert_weights_kernel(const float* __restrict__ Wp,
                                       const float* __restrict__ Wc,
                                       const float* __restrict__ W1,
                                       const float* __restrict__ W2)
{
    int i = blockIdx.x * blockDim.x + threadIdx.x;   // 0..16383
    int j = i >> 7, k = i & 127;
    g_Wt[0 * H * H + i] = wmma::__float_to_tf32(Wp[i]);
    g_Wt[1 * H * H + i] = wmma::__float_to_tf32(Wc[i]);
    g_Wt[2 * H * H + i] = wmma::__float_to_tf32(W1[j * 3 * H + k]);
    g_Wt[3 * H * H + i] = wmma::__float_to_tf32(W1[j * 3 * H + H + k]);
    g_Wt[4 * H * H + i] = wmma::__float_to_tf32(W1[j * 3 * H + 2 * H + k]);
    g_Wt[5 * H * H + i] = wmma::__float_to_tf32(W2[i]);
}

// ---------------- helpers ----------------
__device__ __forceinline__ void pf_l2(const void* p)
{
    asm volatile("prefetch.global.L2 [%0];" :: "l"(p));
}
__device__ __forceinline__ void cp16(unsigned dst_smem, const void* src)
{
    asm volatile("cp.async.cg.shared.global [%0], [%1], 16;" :: "r"(dst_smem), "l"(src));
}
__device__ __forceinline__ void cp_commit()
{
    asm volatile("cp.async.commit_group;");
}
__device__ __forceinline__ void cp_wait_all()
{
    asm volatile("cp.async.wait_group 0;");
}
__device__ __forceinline__ float4 tf32x4(float4 v)
{
    v.x = wmma::__float_to_tf32(v.x);
    v.y = wmma::__float_to_tf32(v.y);
    v.z = wmma::__float_to_tf32(v.z);
    v.w = wmma::__float_to_tf32(v.w);
    return v;
}

// 8 warps on a 64x128 tile: warp w -> rows [wm,wm+16), cols [wn,wn+64)
// B comes from GLOBAL (tf32-pre-rounded, row-major j*H+k -> col_major with ldm=H)
__device__ __forceinline__ void gemm64g(
    const float* __restrict__ Xs, const float* __restrict__ Wg,
    wmma::fragment<wmma::accumulator, 16, 16, 8, float> (&acc)[4],
    int wm, int wn)
{
    #pragma unroll
    for (int j = 0; j < 4; j++)
        wmma::fill_fragment(acc[j], 0.0f);

    #pragma unroll
    for (int k0 = 0; k0 < H; k0 += 8) {
        wmma::fragment<wmma::matrix_a, 16, 16, 8, wmma::precision::tf32, wmma::row_major> a;
        wmma::fragment<wmma::matrix_b, 16, 16, 8, wmma::precision::tf32, wmma::col_major> b[4];
        wmma::load_matrix_sync(a, Xs + wm * XLD + k0, XLD);
        #pragma unroll
        for (int j = 0; j < 4; j++)
            wmma::load_matrix_sync(b[j], Wg + (wn + j * 16) * H + k0, H);
        #pragma unroll
        for (int j = 0; j < 4; j++)
            wmma::mma_sync(acc[j], a, b[j], acc[j]);
    }
}

__device__ __forceinline__ void store_acc64(
    float* __restrict__ Xs,
    wmma::fragment<wmma::accumulator, 16, 16, 8, float> (&acc)[4],
    int wm, int wn)
{
    #pragma unroll
    for (int j = 0; j < 4; j++)
        wmma::store_matrix_sync(Xs + wm * XLD + wn + j * 16, acc[j], XLD,
                                wmma::mem_row_major);
}

// ---------------- node precompute (persistent, 2 CTAs/SM, cp.async pipelined) ----
// A[n] = (leakyrelu(x @ Wenc^T + benc)) @ W1slab^T
__global__ void __launch_bounds__(NTHREADS, 2)
node_kernel(const float* __restrict__ x_src, const float* __restrict__ x_dst,
            const float* __restrict__ bp, const float* __restrict__ bc,
            float* __restrict__ A_src, float* __restrict__ A_dst,
            int n_nodes, int ntiles)
{
    extern __shared__ float sm[];
    float* X[2] = { sm, sm + BM * XLD };

    const int tid  = threadIdx.x;
    const int lane = tid & 31;
    const int w    = tid >> 5;
    const int wm   = (w & 3) * 16;
    const int wn   = (w >> 2) * 64;

    unsigned xb[2];
    xb[0] = (unsigned)__cvta_generic_to_shared(X[0]);
    xb[1] = (unsigned)__cvta_generic_to_shared(X[1]);

    wmma::fragment<wmma::accumulator, 16, 16, 8, float> acc[4];

    for (int half = 0; half < 2; half++) {
        const float* x    = half ? x_dst : x_src;
        const float* benc = half ? bc    : bp;
        const float* Wenc = g_Wt + (half ? 1 : 0) * H * H;
        const float* W1s  = g_Wt + (half ? 3 : 2) * H * H;
        float*       Aout = half ? A_dst : A_src;

        float4 ber = __ldg((const float4*)benc + lane);
        __syncthreads();   // previous half fully done with smem

        // prologue: stage first tile
        int t0 = blockIdx.x;
        if (t0 < ntiles) {
            #pragma unroll
            for (int it = 0; it < 8; it++) {
                int ch = tid + it * NTHREADS;          // 2048 16B chunks
                int m = ch >> 5, off = ch & 31;
                int n = t0 * BM + m; if (n >= n_nodes) n = n_nodes - 1;
                cp16(xb[0] + (unsigned)(m * XLD + off * 4) * 4,
                     x + (size_t)n * H + off * 4);
            }
            cp_commit();
        }

        int lt = 0;
        for (int t = blockIdx.x; t < ntiles; t += gridDim.x, lt++) {
            const int buf = lt & 1, nbuf = buf ^ 1;
            const int tn  = t + gridDim.x;
            float* Xb = X[buf];

            cp_wait_all();
            __syncthreads();

            // tf32 convert pass (in place)
            #pragma unroll
            for (int it = 0; it < 8; it++) {
                int m = w + it * 8;
                float4* p = (float4*)(Xb + m * XLD + lane * 4);
                *p = tf32x4(*p);
            }

            // stage next tile into the other buffer
            if (tn < ntiles) {
                #pragma unroll
                for (int it = 0; it < 8; it++) {
                    int ch = tid + it * NTHREADS;
                    int m = ch >> 5, off = ch & 31;
                    int n = tn * BM + m; if (n >= n_nodes) n = n_nodes - 1;
                    cp16(xb[nbuf] + (unsigned)(m * XLD + off * 4) * 4,
                         x + (size_t)n * H + off * 4);
                }
                cp_commit();
            }
            __syncthreads();

            gemm64g(Xb, Wenc, acc, wm, wn);
            __syncthreads();
            store_acc64(Xb, acc, wm, wn);
            __syncthreads();

            // bias + LeakyReLU
            #pragma unroll
            for (int it = 0; it < 8; it++) {
                int m = w + it * 8;
                float4 v = *(float4*)(Xb + m * XLD + lane * 4);
                v.x += ber.x; v.y += ber.y; v.z += ber.z; v.w += ber.w;
                v.x = (v.x > 0.f) ? v.x : 0.01f * v.x;
                v.y = (v.y > 0.f) ? v.y : 0.01f * v.y;
                v.z = (v.z > 0.f) ? v.z : 0.01f * v.z;
                v.w = (v.w > 0.f) ? v.w : 0.01f * v.w;
                *(float4*)(Xb + m * XLD + lane * 4) = tf32x4(v);
            }
            __syncthreads();

            gemm64g(Xb, W1s, acc, wm, wn);
            __syncthreads();
            store_acc64(Xb, acc, wm, wn);
            __syncthreads();

            #pragma unroll
            for (int it = 0; it < 8; it++) {
                int m = w + it * 8;
                int n = t * BM + m;
                if (n < n_nodes)
                    *((float4*)(Aout + (size_t)n * H) + lane) =
                        *(float4*)(Xb + m * XLD + lane * 4);
            }
            __syncthreads();
        }
    }
}

// ---------------- edge kernel (persistent, 2 CTAs/SM, cp.async pipelined) ----------
__global__ void __launch_bounds__(NTHREADS, 2)
edge_kernel(const float* __restrict__ x_src, const float* __restrict__ x_dst,
            const void* __restrict__ ei,
            const float* __restrict__ b1, const float* __restrict__ b2,
            float* __restrict__ out, int n_edges, int ntiles)
{
    extern __shared__ float sm[];
    float* X[2] = { sm, sm + BM * XLD };
    __shared__ int s_si[2][BM], s_di[2][BM];

    const int tid  = threadIdx.x;
    const int lane = tid & 31;
    const int w    = tid >> 5;
    const int wm   = (w & 3) * 16;
    const int wn   = (w >> 2) * 64;
    const int is64 = g_is64;

    const float* W1d = g_Wt + 4 * H * H;
    const float* W2g = g_Wt + 5 * H * H;

    unsigned xb[2];
    xb[0] = (unsigned)__cvta_generic_to_shared(X[0]);
    xb[1] = (unsigned)__cvta_generic_to_shared(X[1]);

    float4 b1r = __ldg((const float4*)b1 + lane);
    float4 b2r = __ldg((const float4*)b2 + lane);

    const float4* dst4 = (const float4*)x_dst;
    const float4* As4  = (const float4*)g_A_src;
    const float4* Ad4  = (const float4*)g_A_dst;
    float4*       out4 = (float4*)out;

    // prologue: indices + parent cp.async for first tile
    if (blockIdx.x < ntiles && tid < BM) {
        int e = blockIdx.x * BM + tid; if (e >= n_edges) e = n_edges - 1;
        if (is64) {
            s_si[0][tid] = (int)((const long long*)ei)[e];
            s_di[0][tid] = (int)((const long long*)ei)[(size_t)n_edges + e];
        } else {
            s_si[0][tid] = ((const int*)ei)[e];
            s_di[0][tid] = ((const int*)ei)[(size_t)n_edges + e];
        }
    }
    __syncthreads();
    if (blockIdx.x < ntiles) {
        #pragma unroll
        for (int it = 0; it < 8; it++) {
            int ch = tid + it * NTHREADS;
            int m = ch >> 5, off = ch & 31;
            cp16(xb[0] + (unsigned)(m * XLD + off * 4) * 4,
                 x_src + (size_t)s_si[0][m] * H + off * 4);
        }
        cp_commit();
    }

    wmma::fragment<wmma::accumulator, 16, 16, 8, float> acc[4];

    int lt = 0;
    for (int t = blockIdx.x; t < ntiles; t += gridDim.x, lt++) {
        const int buf = lt & 1, nbuf = buf ^ 1;
        const int tn  = t + gridDim.x;
        float* Xb = X[buf];

        // next tile's indices (visible after the sync below)
        if (tn < ntiles && tid < BM) {
            int e = tn * BM + tid; if (e >= n_edges) e = n_edges - 1;
            if (is64) {
                s_si[nbuf][tid] = (int)((const long long*)ei)[e];
                s_di[nbuf][tid] = (int)((const long long*)ei)[(size_t)n_edges + e];
            } else {
                s_si[nbuf][tid] = ((const int*)ei)[e];
                s_di[nbuf][tid] = ((const int*)ei)[(size_t)n_edges + e];
            }
        }

        cp_wait_all();
        __syncthreads();

        // convert pass: diff = |p - c| (p staged in smem, c direct, L2-prefetched)
        // also prefetch this tile's A lines (consumed after GEMM1)
        #pragma unroll
        for (int it = 0; it < 8; it++) {
            int m  = w + it * 8;
            int si = s_si[buf][m], di = s_di[buf][m];
            float4 p = *(float4*)(Xb + m * XLD + lane * 4);
            float4 c = __ldg(dst4 + (size_t)di * 32 + lane);
            if ((lane & 7) == 0) {
                pf_l2(As4 + (size_t)si * 32 + lane);
                pf_l2(Ad4 + (size_t)di * 32 + lane);
            }
            float4 v;
            v.x = fabsf(p.x - c.x); v.y = fabsf(p.y - c.y);
            v.z = fabsf(p.z - c.z); v.w = fabsf(p.w - c.w);
            *(float4*)(Xb + m * XLD + lane * 4) = tf32x4(v);
        }

        // stage next tile's parent rows; prefetch next child rows
        if (tn < ntiles) {
            #pragma unroll
            for (int it = 0; it < 8; it++) {
                int ch = tid + it * NTHREADS;
                int m = ch >> 5, off = ch & 31;
                cp16(xb[nbuf] + (unsigned)(m * XLD + off * 4) * 4,
                     x_src + (size_t)s_si[nbuf][m] * H + off * 4);
            }
            cp_commit();
            if ((lane & 7) == 0) {
                #pragma unroll
                for (int it = 0; it < 8; it++) {
                    int m = w + it * 8;
                    pf_l2(dst4 + (size_t)s_di[nbuf][m] * 32 + lane);
                }
            }
        }
        __syncthreads();

        gemm64g(Xb, W1d, acc, wm, wn);
        __syncthreads();
        store_acc64(Xb, acc, wm, wn);
        __syncthreads();

        // epilogue: + A_src + A_dst + b1, ReLU
        #pragma unroll
        for (int it = 0; it < 8; it++) {
            int m  = w + it * 8;
            int si = s_si[buf][m], di = s_di[buf][m];
            float4 as = __ldg(As4 + (size_t)si * 32 + lane);
            float4 ad = __ldg(Ad4 + (size_t)di * 32 + lane);
            float4 v  = *(float4*)(Xb + m * XLD + lane * 4);
            v.x = fmaxf(v.x + as.x + ad.x + b1r.x, 0.f);
            v.y = fmaxf(v.y + as.y + ad.y + b1r.y, 0.f);
            v.z = fmaxf(v.z + as.z + ad.z + b1r.z, 0.f);
            v.w = fmaxf(v.w + as.w + ad.w + b1r.w, 0.f);
            *(float4*)(Xb + m * XLD + lane * 4) = tf32x4(v);
        }
        __syncthreads();

        gemm64g(Xb, W2g, acc, wm, wn);
        __syncthreads();
        store_acc64(Xb, acc, wm, wn);
        __syncthreads();

        // output + b2 (streaming stores)
        #pragma unroll
        for (int it = 0; it < 8; it++) {
            int m = w + it * 8;
            int e = t * BM + m;
            if (e < n_edges) {
                float4 v = *(float4*)(Xb + m * XLD + lane * 4);
                v.x += b2r.x; v.y += b2r.y; v.z += b2r.z; v.w += b2r.w;
                __stcs(out4 + (size_t)e * 32 + lane, v);
            }
        }
        __syncthreads();
    }
}

// ---------------- launch ----------------
extern "C" void kernel_launch(void* const* d_in, const int* in_sizes, int n_in,
                              void* d_out, int out_size)
{
    const float* x_src = (const float*)d_in[0];
    const float* x_dst = (const float*)d_in[1];
    const void*  ei    = d_in[2];
    const float* Wp    = (const float*)d_in[3];
    const float* bp    = (const float*)d_in[4];
    const float* Wc    = (const float*)d_in[5];
    const float* bc    = (const float*)d_in[6];
    const float* W1    = (const float*)d_in[7];
    const float* b1    = (const float*)d_in[8];
    const float* W2    = (const float*)d_in[9];
    const float* b2    = (const float*)d_in[10];

    const int n_nodes = in_sizes[0] / H;
    const int n_edges = in_sizes[2] / 2;

    static int attr_set = 0;
    if (!attr_set) {
        cudaFuncSetAttribute(node_kernel, cudaFuncAttributeMaxDynamicSharedMemorySize, SMEM_BYTES);
        cudaFuncSetAttribute(edge_kernel, cudaFuncAttributeMaxDynamicSharedMemorySize, SMEM_BYTES);
        attr_set = 1;
    }

    detect_idx_kernel<<<1, 64>>>((const int*)ei);
    convert_weights_kernel<<<H * H / NTHREADS, NTHREADS>>>(Wp, Wc, W1, W2);

    float* A_src_ptr;  cudaGetSymbolAddress((void**)&A_src_ptr, g_A_src);
    float* A_dst_ptr;  cudaGetSymbolAddress((void**)&A_dst_ptr, g_A_dst);

    const int node_tiles = (n_nodes + BM - 1) / BM;
    const int ngrid = node_tiles < 2 * NSM ? node_tiles : 2 * NSM;
    node_kernel<<<ngrid, NTHREADS, SMEM_BYTES>>>(
        x_src, x_dst, bp, bc, A_src_ptr, A_dst_ptr, n_nodes, node_tiles);

    const int edge_tiles = (n_edges + BM - 1) / BM;
    const int egrid = edge_tiles < 2 * NSM ? edge_tiles : 2 * NSM;
    edge_kernel<<<egrid, NTHREADS, SMEM_BYTES>>>(
        x_src, x_dst, ei, b1, b2, (float*)d_out, n_edges, edge_tiles);
}

// round 8
// speedup vs baseline: 1.6722x; 1.6722x over previous
#include <cuda_runtime.h>
#include <cstdint>
#include <mma.h>
#include <math.h>

using namespace nvcuda;

#define H        128
#define BM       64       // rows per tile
#define XLD      132      // padded leading dim (floats)
#define WLD      132
#define NTHREADS 512      // 8 consumer warps + 8 producer warps
#define NSM      152
#define SMEM_BYTES ((2 * BM * XLD + 2 * H * WLD) * 4)

// ---------------- scratch ----------------
#define MAX_NODES 100000
__device__ int   g_is64;
__device__ float g_A_src[(size_t)MAX_NODES * H];
__device__ float g_A_dst[(size_t)MAX_NODES * H];

// ---------------- named barriers ----------------
#define BSYNC512(id)  asm volatile("bar.sync %0, 512;"   :: "r"(id) : "memory")
#define BARR512(id)   asm volatile("bar.arrive %0, 512;" :: "r"(id) : "memory")
#define BSYNC256(id)  asm volatile("bar.sync %0, 256;"   :: "r"(id) : "memory")

// ---------------- int32/int64 detection (parallel) ----------------
__global__ void detect_idx_kernel(const int* __restrict__ ei)
{
    int odd = ei[threadIdx.x * 2 + 1];
    unsigned any = __ballot_sync(0xFFFFFFFFu, odd != 0);
    __shared__ unsigned s[2];
    if ((threadIdx.x & 31) == 0) s[threadIdx.x >> 5] = any;
    __syncthreads();
    if (threadIdx.x == 0) g_is64 = (s[0] | s[1]) ? 0 : 1;
}

// ---------------- helpers ----------------
__device__ __forceinline__ float4 tf32x4(float4 v)
{
    v.x = wmma::__float_to_tf32(v.x);
    v.y = wmma::__float_to_tf32(v.y);
    v.z = wmma::__float_to_tf32(v.z);
    v.w = wmma::__float_to_tf32(v.w);
    return v;
}

// 8 consumer warps on a 64x128 tile: warp w -> rows [wm,wm+16), cols [wn,wn+64)
__device__ __forceinline__ void gemm64s(
    const float* __restrict__ Xs, const float* __restrict__ Ws,
    wmma::fragment<wmma::accumulator, 16, 16, 8, float> (&acc)[4],
    int wm, int wn)
{
    #pragma unroll
    for (int j = 0; j < 4; j++)
        wmma::fill_fragment(acc[j], 0.0f);

    #pragma unroll
    for (int k0 = 0; k0 < H; k0 += 8) {
        wmma::fragment<wmma::matrix_a, 16, 16, 8, wmma::precision::tf32, wmma::row_major> a;
        wmma::fragment<wmma::matrix_b, 16, 16, 8, wmma::precision::tf32, wmma::col_major> b[4];
        wmma::load_matrix_sync(a, Xs + wm * XLD + k0, XLD);
        #pragma unroll
        for (int j = 0; j < 4; j++)
            wmma::load_matrix_sync(b[j], Ws + (wn + j * 16) * WLD + k0, WLD);
        #pragma unroll
        for (int j = 0; j < 4; j++)
            wmma::mma_sync(acc[j], a, b[j], acc[j]);
    }
}

__device__ __forceinline__ void store_acc64(
    float* __restrict__ Xs,
    wmma::fragment<wmma::accumulator, 16, 16, 8, float> (&acc)[4],
    int wm, int wn)
{
    #pragma unroll
    for (int j = 0; j < 4; j++)
        wmma::store_matrix_sync(Xs + wm * XLD + wn + j * 16, acc[j], XLD,
                                wmma::mem_row_major);
}

// =====================================================================
// NODE kernel: A[n] = (leakyrelu(x @ Wenc^T + benc)) @ W1slab^T
// Warp-specialized: warps 0-7 tensor, 8-15 memory.
// =====================================================================
__global__ void __launch_bounds__(NTHREADS, 1)
node_kernel(const float* __restrict__ x_src, const float* __restrict__ x_dst,
            const float* __restrict__ Wp, const float* __restrict__ bp,
            const float* __restrict__ Wc, const float* __restrict__ bc,
            const float* __restrict__ W1,
            float* __restrict__ A_src, float* __restrict__ A_dst,
            int n_nodes, int ntiles)
{
    extern __shared__ float sm[];
    float* X[2] = { sm, sm + BM * XLD };
    float* Ws   = sm + 2 * BM * XLD;
    float* W1s  = Ws + H * WLD;

    const int tid  = threadIdx.x;
    const int lane = tid & 31;
    const int w    = tid >> 5;
    const bool prod = (w >= 8);
    const int pw   = w - 8;
    const int wm   = (w & 3) * 16;
    const int wn   = (w >> 2) * 64;
    const int G    = gridDim.x;

    int K = 0;
    if ((int)blockIdx.x < ntiles) K = (ntiles - 1 - (int)blockIdx.x) / G + 1;

    for (int half = 0; half < 2; half++) {
        const float* x    = half ? x_dst : x_src;
        const float* Wenc = half ? Wc    : Wp;
        const float* benc = half ? bc    : bp;
        const int    koff = half ? H     : 0;
        float*       Aout = half ? A_dst : A_src;

        __syncthreads();   // drain previous half
        for (int idx = tid; idx < H * 32; idx += NTHREADS) {
            int j = idx >> 5, k4 = idx & 31;
            float4 we = __ldg((const float4*)(Wenc + (size_t)j * H) + k4);
            float4 w1 = __ldg((const float4*)(W1 + (size_t)j * 3 * H + koff) + k4);
            *(float4*)(Ws  + j * WLD + k4 * 4) = tf32x4(we);
            *(float4*)(W1s + j * WLD + k4 * 4) = tf32x4(w1);
        }
        __syncthreads();

        if (!prod) {
            // ---------- consumer (tensor) ----------
            wmma::fragment<wmma::accumulator, 16, 16, 8, float> acc[4];
            for (int k = 0; k <= K + 1; k++) {
                if (k < K) {
                    int b = k & 1;
                    BSYNC512(1 + b);                 // X ready
                    gemm64s(X[b], Ws, acc, wm, wn);
                    BSYNC256(10);
                    store_acc64(X[b], acc, wm, wn);
                    BARR512(3 + b);                  // Y ready
                }
                int j = k - 1;
                if (j >= 0 && j < K) {
                    int b = j & 1;
                    BSYNC512(5 + b);                 // Y' ready
                    gemm64s(X[b], W1s, acc, wm, wn);
                    BSYNC256(10);
                    store_acc64(X[b], acc, wm, wn);
                    BARR512(7 + b);                  // Z ready
                }
            }
        } else {
            // ---------- producer (memory) ----------
            float4 ber = __ldg((const float4*)benc + lane);
            const float4* x4 = (const float4*)x;
            float4*       A4 = (float4*)Aout;
            for (int k = 0; k <= K + 1; k++) {
                int s = k - 2;
                if (s >= 0 && s < K) {               // store A(s)
                    int b = s & 1;
                    BSYNC512(7 + b);
                    float* Xb = X[b];
                    int base = ((int)blockIdx.x + s * G) * BM;
                    #pragma unroll
                    for (int it = 0; it < 8; it++) {
                        int m = pw + it * 8;
                        int n = base + m;
                        if (n < n_nodes)
                            A4[(size_t)n * 32 + lane] =
                                *(float4*)(Xb + m * XLD + lane * 4);
                    }
                }
                if (k < K) {                         // gather X(k)
                    int b = k & 1;
                    float* Xb = X[b];
                    int base = ((int)blockIdx.x + k * G) * BM;
                    #pragma unroll
                    for (int it = 0; it < 8; it++) {
                        int m = pw + it * 8;
                        int n = base + m; if (n >= n_nodes) n = n_nodes - 1;
                        float4 v = __ldg(x4 + (size_t)n * 32 + lane);
                        *(float4*)(Xb + m * XLD + lane * 4) = tf32x4(v);
                    }
                    BARR512(1 + b);
                }
                int e = k - 1;
                if (e >= 0 && e < K) {               // epilogue(e): bias + lrelu
                    int b = e & 1;
                    BSYNC512(3 + b);
                    float* Xb = X[b];
                    #pragma unroll
                    for (int it = 0; it < 8; it++) {
                        int m = pw + it * 8;
                        float4 v = *(float4*)(Xb + m * XLD + lane * 4);
                        v.x += ber.x; v.y += ber.y; v.z += ber.z; v.w += ber.w;
                        v.x = (v.x > 0.f) ? v.x : 0.01f * v.x;
                        v.y = (v.y > 0.f) ? v.y : 0.01f * v.y;
                        v.z = (v.z > 0.f) ? v.z : 0.01f * v.z;
                        v.w = (v.w > 0.f) ? v.w : 0.01f * v.w;
                        *(float4*)(Xb + m * XLD + lane * 4) = tf32x4(v);
                    }
                    BARR512(5 + b);
                }
            }
        }
    }
}

// =====================================================================
// EDGE kernel: out[e] = relu(|p-c|@W1d^T + A_src[si] + A_dst[di] + b1) @ W2^T + b2
// Warp-specialized producer/consumer.
// Index buffers are 4-deep: at producer iteration k, slot k&3 is read by the
// gather, (k-1)&3 by the epilogue, (k+1)&3 written by staging — all distinct.
// =====================================================================
__global__ void __launch_bounds__(NTHREADS, 1)
edge_kernel(const float* __restrict__ x_src, const float* __restrict__ x_dst,
            const void* __restrict__ ei,
            const float* __restrict__ W1, const float* __restrict__ b1,
            const float* __restrict__ W2, const float* __restrict__ b2,
            float* __restrict__ out, int n_edges, int ntiles)
{
    extern __shared__ float sm[];
    float* X[2] = { sm, sm + BM * XLD };
    float* W1s  = sm + 2 * BM * XLD;
    float* W2s  = W1s + H * WLD;
    __shared__ int s_si[4][BM], s_di[4][BM];

    const int tid  = threadIdx.x;
    const int lane = tid & 31;
    const int w    = tid >> 5;
    const bool prod = (w >= 8);
    const int pw   = w - 8;
    const int wm   = (w & 3) * 16;
    const int wn   = (w >> 2) * 64;
    const int G    = gridDim.x;
    const int is64 = g_is64;

    int K = 0;
    if ((int)blockIdx.x < ntiles) K = (ntiles - 1 - (int)blockIdx.x) / G + 1;

    // weights -> smem (tf32-rounded)
    for (int idx = tid; idx < H * 32; idx += NTHREADS) {
        int j = idx >> 5, k4 = idx & 31;
        float4 w1 = __ldg((const float4*)(W1 + (size_t)j * 3 * H + 2 * H) + k4);
        float4 w2 = __ldg((const float4*)(W2 + (size_t)j * H) + k4);
        *(float4*)(W1s + j * WLD + k4 * 4) = tf32x4(w1);
        *(float4*)(W2s + j * WLD + k4 * 4) = tf32x4(w2);
    }
    // preload indices of tile 0 into slot 0
    if (K > 0 && tid < BM) {
        int e = (int)blockIdx.x * BM + tid; if (e >= n_edges) e = n_edges - 1;
        if (is64) {
            s_si[0][tid] = (int)((const long long*)ei)[e];
            s_di[0][tid] = (int)((const long long*)ei)[(size_t)n_edges + e];
        } else {
            s_si[0][tid] = ((const int*)ei)[e];
            s_di[0][tid] = ((const int*)ei)[(size_t)n_edges + e];
        }
    }
    __syncthreads();

    if (!prod) {
        // ---------- consumer (tensor) ----------
        wmma::fragment<wmma::accumulator, 16, 16, 8, float> acc[4];
        for (int k = 0; k <= K + 1; k++) {
            if (k < K) {
                int b = k & 1;
                BSYNC512(1 + b);                     // diff ready
                gemm64s(X[b], W1s, acc, wm, wn);
                BSYNC256(10);
                store_acc64(X[b], acc, wm, wn);
                BARR512(3 + b);                      // Y ready
            }
            int j = k - 1;
            if (j >= 0 && j < K) {
                int b = j & 1;
                BSYNC512(5 + b);                     // Y' ready
                gemm64s(X[b], W2s, acc, wm, wn);
                BSYNC256(10);
                store_acc64(X[b], acc, wm, wn);
                BARR512(7 + b);                      // Z ready
            }
        }
    } else {
        // ---------- producer (memory) ----------
        float4 b1r = __ldg((const float4*)b1 + lane);
        float4 b2r = __ldg((const float4*)b2 + lane);
        const float4* src4 = (const float4*)x_src;
        const float4* dst4 = (const float4*)x_dst;
        const float4* As4  = (const float4*)g_A_src;
        const float4* Ad4  = (const float4*)g_A_dst;
        float4*       out4 = (float4*)out;
        const int ptid = tid - 256;

        for (int k = 0; k <= K + 1; k++) {
            BSYNC256(9);                             // staged idx visibility
            int s = k - 2;
            if (s >= 0 && s < K) {                   // store out(s)
                int b = s & 1;
                BSYNC512(7 + b);
                float* Xb = X[b];
                int base = ((int)blockIdx.x + s * G) * BM;
                #pragma unroll
                for (int it = 0; it < 8; it++) {
                    int m = pw + it * 8;
                    int e = base + m;
                    if (e < n_edges) {
                        float4 v = *(float4*)(Xb + m * XLD + lane * 4);
                        v.x += b2r.x; v.y += b2r.y; v.z += b2r.z; v.w += b2r.w;
                        __stcs(out4 + (size_t)e * 32 + lane, v);
                    }
                }
            }
            if (k < K) {                             // gather diff(k)
                int b = k & 1;
                const int ib = k & 3;
                float* Xb = X[b];
                #pragma unroll
                for (int it = 0; it < 8; it++) {
                    int m  = pw + it * 8;
                    int si = s_si[ib][m], di = s_di[ib][m];
                    float4 p = __ldg(src4 + (size_t)si * 32 + lane);
                    float4 c = __ldg(dst4 + (size_t)di * 32 + lane);
                    float4 v;
                    v.x = fabsf(p.x - c.x); v.y = fabsf(p.y - c.y);
                    v.z = fabsf(p.z - c.z); v.w = fabsf(p.w - c.w);
                    *(float4*)(Xb + m * XLD + lane * 4) = tf32x4(v);
                }
                BARR512(1 + b);
            }
            int e = k - 1;
            if (e >= 0 && e < K) {                   // epilogue(e): +A+b1, relu
                int b = e & 1;
                const int ib = e & 3;
                BSYNC512(3 + b);
                float* Xb = X[b];
                #pragma unroll
                for (int it = 0; it < 8; it++) {
                    int m  = pw + it * 8;
                    int si = s_si[ib][m], di = s_di[ib][m];
                    float4 as = __ldg(As4 + (size_t)si * 32 + lane);
                    float4 ad = __ldg(Ad4 + (size_t)di * 32 + lane);
                    float4 v  = *(float4*)(Xb + m * XLD + lane * 4);
                    v.x = fmaxf(v.x + as.x + ad.x + b1r.x, 0.f);
                    v.y = fmaxf(v.y + as.y + ad.y + b1r.y, 0.f);
                    v.z = fmaxf(v.z + as.z + ad.z + b1r.z, 0.f);
                    v.w = fmaxf(v.w + as.w + ad.w + b1r.w, 0.f);
                    *(float4*)(Xb + m * XLD + lane * 4) = tf32x4(v);
                }
                BARR512(5 + b);
            }
            if (k + 1 < K && ptid < BM) {            // stage idx(k+1) into slot (k+1)&3
                int tn = (int)blockIdx.x + (k + 1) * G;
                int ee = tn * BM + ptid; if (ee >= n_edges) ee = n_edges - 1;
                const int ib = (k + 1) & 3;
                if (is64) {
                    s_si[ib][ptid] = (int)((const long long*)ei)[ee];
                    s_di[ib][ptid] = (int)((const long long*)ei)[(size_t)n_edges + ee];
                } else {
                    s_si[ib][ptid] = ((const int*)ei)[ee];
                    s_di[ib][ptid] = ((const int*)ei)[(size_t)n_edges + ee];
                }
            }
        }
    }
}

// ---------------- launch ----------------
extern "C" void kernel_launch(void* const* d_in, const int* in_sizes, int n_in,
                              void* d_out, int out_size)
{
    const float* x_src = (const float*)d_in[0];
    const float* x_dst = (const float*)d_in[1];
    const void*  ei    = d_in[2];
    const float* Wp    = (const float*)d_in[3];
    const float* bp    = (const float*)d_in[4];
    const float* Wc    = (const float*)d_in[5];
    const float* bc    = (const float*)d_in[6];
    const float* W1    = (const float*)d_in[7];
    const float* b1    = (const float*)d_in[8];
    const float* W2    = (const float*)d_in[9];
    const float* b2    = (const float*)d_in[10];

    const int n_nodes = in_sizes[0] / H;
    const int n_edges = in_sizes[2] / 2;

    static int attr_set = 0;
    if (!attr_set) {
        cudaFuncSetAttribute(node_kernel, cudaFuncAttributeMaxDynamicSharedMemorySize, SMEM_BYTES);
        cudaFuncSetAttribute(edge_kernel, cudaFuncAttributeMaxDynamicSharedMemorySize, SMEM_BYTES);
        attr_set = 1;
    }

    detect_idx_kernel<<<1, 64>>>((const int*)ei);

    float* A_src_ptr;  cudaGetSymbolAddress((void**)&A_src_ptr, g_A_src);
    float* A_dst_ptr;  cudaGetSymbolAddress((void**)&A_dst_ptr, g_A_dst);

    const int node_tiles = (n_nodes + BM - 1) / BM;
    const int ngrid = node_tiles < NSM ? node_tiles : NSM;
    node_kernel<<<ngrid, NTHREADS, SMEM_BYTES>>>(
        x_src, x_dst, Wp, bp, Wc, bc, W1, A_src_ptr, A_dst_ptr, n_nodes, node_tiles);

    const int edge_tiles = (n_edges + BM - 1) / BM;
    const int egrid = edge_tiles < NSM ? edge_tiles : NSM;
    edge_kernel<<<egrid, NTHREADS, SMEM_BYTES>>>(
        x_src, x_dst, ei, W1, b1, W2, b2, (float*)d_out, n_edges, edge_tiles);
}

// round 9
// speedup vs baseline: 1.9042x; 1.1387x over previous
#include <cuda_runtime.h>
#include <cstdint>
#include <mma.h>
#include <math.h>

using namespace nvcuda;

#define H        128
#define BM       64       // rows per tile
#define XLD      132      // padded leading dim (floats)
#define WLD      132
#define NTHREADS 512      // 8 consumer warps + 8 producer warps
#define NSM      152
#define SMEM_BYTES ((2 * BM * XLD + 2 * H * WLD) * 4)

// ---------------- scratch ----------------
#define MAX_NODES 100000
__device__ int   g_is64;
__device__ float g_A_src[(size_t)MAX_NODES * H];
__device__ float g_A_dst[(size_t)MAX_NODES * H];

// ---------------- named barriers ----------------
#define BSYNC512(id)  asm volatile("bar.sync %0, 512;"   :: "r"(id) : "memory")
#define BARR512(id)   asm volatile("bar.arrive %0, 512;" :: "r"(id) : "memory")
#define BSYNC256(id)  asm volatile("bar.sync %0, 256;"   :: "r"(id) : "memory")

// ---------------- int32/int64 detection (parallel) ----------------
__global__ void detect_idx_kernel(const int* __restrict__ ei)
{
    int odd = ei[threadIdx.x * 2 + 1];
    unsigned any = __ballot_sync(0xFFFFFFFFu, odd != 0);
    __shared__ unsigned s[2];
    if ((threadIdx.x & 31) == 0) s[threadIdx.x >> 5] = any;
    __syncthreads();
    if (threadIdx.x == 0) g_is64 = (s[0] | s[1]) ? 0 : 1;
}

// ---------------- helpers ----------------
__device__ __forceinline__ void pf_l2(const void* p)
{
    asm volatile("prefetch.global.L2 [%0];" :: "l"(p));
}

__device__ __forceinline__ float4 tf32x4(float4 v)
{
    v.x = wmma::__float_to_tf32(v.x);
    v.y = wmma::__float_to_tf32(v.y);
    v.z = wmma::__float_to_tf32(v.z);
    v.w = wmma::__float_to_tf32(v.w);
    return v;
}

// 8 consumer warps on a 64x128 tile: warp w -> rows [wm,wm+32), cols [wn,wn+32)
__device__ __forceinline__ void gemm64s(
    const float* __restrict__ Xs, const float* __restrict__ Ws,
    wmma::fragment<wmma::accumulator, 16, 16, 8, float> (&acc)[2][2],
    int wm, int wn)
{
    #pragma unroll
    for (int i = 0; i < 2; i++)
        #pragma unroll
        for (int j = 0; j < 2; j++)
            wmma::fill_fragment(acc[i][j], 0.0f);

    #pragma unroll
    for (int k0 = 0; k0 < H; k0 += 8) {
        wmma::fragment<wmma::matrix_a, 16, 16, 8, wmma::precision::tf32, wmma::row_major> a[2];
        wmma::fragment<wmma::matrix_b, 16, 16, 8, wmma::precision::tf32, wmma::col_major> b[2];
        #pragma unroll
        for (int i = 0; i < 2; i++)
            wmma::load_matrix_sync(a[i], Xs + (wm + i * 16) * XLD + k0, XLD);
        #pragma unroll
        for (int j = 0; j < 2; j++)
            wmma::load_matrix_sync(b[j], Ws + (wn + j * 16) * WLD + k0, WLD);
        #pragma unroll
        for (int i = 0; i < 2; i++)
            #pragma unroll
            for (int j = 0; j < 2; j++)
                wmma::mma_sync(acc[i][j], a[i], b[j], acc[i][j]);
    }
}

__device__ __forceinline__ void store_acc64(
    float* __restrict__ Xs,
    wmma::fragment<wmma::accumulator, 16, 16, 8, float> (&acc)[2][2],
    int wm, int wn)
{
    #pragma unroll
    for (int i = 0; i < 2; i++)
        #pragma unroll
        for (int j = 0; j < 2; j++)
            wmma::store_matrix_sync(Xs + (wm + i * 16) * XLD + wn + j * 16,
                                    acc[i][j], XLD, wmma::mem_row_major);
}

// =====================================================================
// NODE kernel: A[n] = (leakyrelu(x @ Wenc^T + benc)) @ W1slab^T
// Warp-specialized: warps 0-7 tensor, 8-15 memory.
// =====================================================================
__global__ void __launch_bounds__(NTHREADS, 1)
node_kernel(const float* __restrict__ x_src, const float* __restrict__ x_dst,
            const float* __restrict__ Wp, const float* __restrict__ bp,
            const float* __restrict__ Wc, const float* __restrict__ bc,
            const float* __restrict__ W1,
            float* __restrict__ A_src, float* __restrict__ A_dst,
            int n_nodes, int ntiles)
{
    extern __shared__ float sm[];
    float* X[2] = { sm, sm + BM * XLD };
    float* Ws   = sm + 2 * BM * XLD;
    float* W1s  = Ws + H * WLD;

    const int tid  = threadIdx.x;
    const int lane = tid & 31;
    const int w    = tid >> 5;
    const bool prod = (w >= 8);
    const int pw   = w - 8;
    const int wm   = (w & 1) * 32;
    const int wn   = (w >> 1) * 32;
    const int G    = gridDim.x;

    int K = 0;
    if ((int)blockIdx.x < ntiles) K = (ntiles - 1 - (int)blockIdx.x) / G + 1;

    for (int half = 0; half < 2; half++) {
        const float* x    = half ? x_dst : x_src;
        const float* Wenc = half ? Wc    : Wp;
        const float* benc = half ? bc    : bp;
        const int    koff = half ? H     : 0;
        float*       Aout = half ? A_dst : A_src;

        __syncthreads();   // drain previous half
        for (int idx = tid; idx < H * 32; idx += NTHREADS) {
            int j = idx >> 5, k4 = idx & 31;
            float4 we = __ldg((const float4*)(Wenc + (size_t)j * H) + k4);
            float4 w1 = __ldg((const float4*)(W1 + (size_t)j * 3 * H + koff) + k4);
            *(float4*)(Ws  + j * WLD + k4 * 4) = tf32x4(we);
            *(float4*)(W1s + j * WLD + k4 * 4) = tf32x4(w1);
        }
        __syncthreads();

        if (!prod) {
            // ---------- consumer (tensor) ----------
            wmma::fragment<wmma::accumulator, 16, 16, 8, float> acc[2][2];
            for (int k = 0; k <= K + 1; k++) {
                if (k < K) {
                    int b = k & 1;
                    BSYNC512(1 + b);                 // X ready
                    gemm64s(X[b], Ws, acc, wm, wn);
                    BSYNC256(10);
                    store_acc64(X[b], acc, wm, wn);
                    BARR512(3 + b);                  // Y ready
                }
                int j = k - 1;
                if (j >= 0 && j < K) {
                    int b = j & 1;
                    BSYNC512(5 + b);                 // Y' ready
                    gemm64s(X[b], W1s, acc, wm, wn);
                    BSYNC256(10);
                    store_acc64(X[b], acc, wm, wn);
                    BARR512(7 + b);                  // Z ready
                }
            }
        } else {
            // ---------- producer (memory) ----------
            float4 ber = __ldg((const float4*)benc + lane);
            const float4* x4 = (const float4*)x;
            float4*       A4 = (float4*)Aout;
            for (int k = 0; k <= K + 1; k++) {
                int s = k - 2;
                if (s >= 0 && s < K) {               // store A(s)
                    int b = s & 1;
                    BSYNC512(7 + b);
                    float* Xb = X[b];
                    int base = ((int)blockIdx.x + s * G) * BM;
                    #pragma unroll
                    for (int it = 0; it < 8; it++) {
                        int m = pw + it * 8;
                        int n = base + m;
                        if (n < n_nodes)
                            A4[(size_t)n * 32 + lane] =
                                *(float4*)(Xb + m * XLD + lane * 4);
                    }
                }
                if (k < K) {                         // gather X(k) + prefetch X(k+1)
                    int b = k & 1;
                    float* Xb = X[b];
                    int base  = ((int)blockIdx.x + k * G) * BM;
                    int basen = ((int)blockIdx.x + (k + 1) * G) * BM;
                    bool pf = ((k + 1) < K) && ((lane & 7) == 0);
                    #pragma unroll
                    for (int it = 0; it < 8; it++) {
                        int m = pw + it * 8;
                        int n = base + m; if (n >= n_nodes) n = n_nodes - 1;
                        float4 v = __ldg(x4 + (size_t)n * 32 + lane);
                        if (pf) {
                            int nn = basen + m; if (nn >= n_nodes) nn = n_nodes - 1;
                            pf_l2(x4 + (size_t)nn * 32 + lane);
                        }
                        *(float4*)(Xb + m * XLD + lane * 4) = tf32x4(v);
                    }
                    BARR512(1 + b);
                }
                int e = k - 1;
                if (e >= 0 && e < K) {               // epilogue(e): bias + lrelu
                    int b = e & 1;
                    BSYNC512(3 + b);
                    float* Xb = X[b];
                    #pragma unroll
                    for (int it = 0; it < 8; it++) {
                        int m = pw + it * 8;
                        float4 v = *(float4*)(Xb + m * XLD + lane * 4);
                        v.x += ber.x; v.y += ber.y; v.z += ber.z; v.w += ber.w;
                        v.x = (v.x > 0.f) ? v.x : 0.01f * v.x;
                        v.y = (v.y > 0.f) ? v.y : 0.01f * v.y;
                        v.z = (v.z > 0.f) ? v.z : 0.01f * v.z;
                        v.w = (v.w > 0.f) ? v.w : 0.01f * v.w;
                        *(float4*)(Xb + m * XLD + lane * 4) = tf32x4(v);
                    }
                    BARR512(5 + b);
                }
            }
        }
    }
}

// =====================================================================
// EDGE kernel: out[e] = relu(|p-c|@W1d^T + A_src[si] + A_dst[di] + b1) @ W2^T + b2
// Warp-specialized producer/consumer, 4-deep index slots staged 2 tiles ahead,
// L2 prefetch of next tile's x and A rows one full stage before use.
// At iteration k, slots touched: k (gather), k-1 (epilogue), k+1 (prefetch read),
// k+2 (staging write) — pairwise distinct mod 4.
// =====================================================================
__global__ void __launch_bounds__(NTHREADS, 1)
edge_kernel(const float* __restrict__ x_src, const float* __restrict__ x_dst,
            const void* __restrict__ ei,
            const float* __restrict__ W1, const float* __restrict__ b1,
            const float* __restrict__ W2, const float* __restrict__ b2,
            float* __restrict__ out, int n_edges, int ntiles)
{
    extern __shared__ float sm[];
    float* X[2] = { sm, sm + BM * XLD };
    float* W1s  = sm + 2 * BM * XLD;
    float* W2s  = W1s + H * WLD;
    __shared__ int s_si[4][BM], s_di[4][BM];

    const int tid  = threadIdx.x;
    const int lane = tid & 31;
    const int w    = tid >> 5;
    const bool prod = (w >= 8);
    const int pw   = w - 8;
    const int wm   = (w & 1) * 32;
    const int wn   = (w >> 1) * 32;
    const int G    = gridDim.x;
    const int is64 = g_is64;

    int K = 0;
    if ((int)blockIdx.x < ntiles) K = (ntiles - 1 - (int)blockIdx.x) / G + 1;

    // weights -> smem (tf32-rounded)
    for (int idx = tid; idx < H * 32; idx += NTHREADS) {
        int j = idx >> 5, k4 = idx & 31;
        float4 w1 = __ldg((const float4*)(W1 + (size_t)j * 3 * H + 2 * H) + k4);
        float4 w2 = __ldg((const float4*)(W2 + (size_t)j * H) + k4);
        *(float4*)(W1s + j * WLD + k4 * 4) = tf32x4(w1);
        *(float4*)(W2s + j * WLD + k4 * 4) = tf32x4(w2);
    }
    // preload indices of tiles 0 and 1
    if (K > 0 && tid < BM) {
        int e = (int)blockIdx.x * BM + tid; if (e >= n_edges) e = n_edges - 1;
        if (is64) {
            s_si[0][tid] = (int)((const long long*)ei)[e];
            s_di[0][tid] = (int)((const long long*)ei)[(size_t)n_edges + e];
        } else {
            s_si[0][tid] = ((const int*)ei)[e];
            s_di[0][tid] = ((const int*)ei)[(size_t)n_edges + e];
        }
    }
    if (K > 1 && tid < BM) {
        int e = ((int)blockIdx.x + G) * BM + tid; if (e >= n_edges) e = n_edges - 1;
        if (is64) {
            s_si[1][tid] = (int)((const long long*)ei)[e];
            s_di[1][tid] = (int)((const long long*)ei)[(size_t)n_edges + e];
        } else {
            s_si[1][tid] = ((const int*)ei)[e];
            s_di[1][tid] = ((const int*)ei)[(size_t)n_edges + e];
        }
    }
    __syncthreads();

    if (!prod) {
        // ---------- consumer (tensor) ----------
        wmma::fragment<wmma::accumulator, 16, 16, 8, float> acc[2][2];
        for (int k = 0; k <= K + 1; k++) {
            if (k < K) {
                int b = k & 1;
                BSYNC512(1 + b);                     // diff ready
                gemm64s(X[b], W1s, acc, wm, wn);
                BSYNC256(10);
                store_acc64(X[b], acc, wm, wn);
                BARR512(3 + b);                      // Y ready
            }
            int j = k - 1;
            if (j >= 0 && j < K) {
                int b = j & 1;
                BSYNC512(5 + b);                     // Y' ready
                gemm64s(X[b], W2s, acc, wm, wn);
                BSYNC256(10);
                store_acc64(X[b], acc, wm, wn);
                BARR512(7 + b);                      // Z ready
            }
        }
    } else {
        // ---------- producer (memory) ----------
        float4 b1r = __ldg((const float4*)b1 + lane);
        float4 b2r = __ldg((const float4*)b2 + lane);
        const float4* src4 = (const float4*)x_src;
        const float4* dst4 = (const float4*)x_dst;
        const float4* As4  = (const float4*)g_A_src;
        const float4* Ad4  = (const float4*)g_A_dst;
        float4*       out4 = (float4*)out;
        const int ptid = tid - 256;

        for (int k = 0; k <= K + 1; k++) {
            BSYNC256(9);                             // staged idx visibility
            int s = k - 2;
            if (s >= 0 && s < K) {                   // store out(s)
                int b = s & 1;
                BSYNC512(7 + b);
                float* Xb = X[b];
                int base = ((int)blockIdx.x + s * G) * BM;
                #pragma unroll
                for (int it = 0; it < 8; it++) {
                    int m = pw + it * 8;
                    int e = base + m;
                    if (e < n_edges) {
                        float4 v = *(float4*)(Xb + m * XLD + lane * 4);
                        v.x += b2r.x; v.y += b2r.y; v.z += b2r.z; v.w += b2r.w;
                        __stcs(out4 + (size_t)e * 32 + lane, v);
                    }
                }
            }
            if (k < K) {                             // gather diff(k)
                int b = k & 1;
                const int ib = k & 3;
                float* Xb = X[b];
                #pragma unroll
                for (int it = 0; it < 8; it++) {
                    int m  = pw + it * 8;
                    int si = s_si[ib][m], di = s_di[ib][m];
                    float4 p = __ldg(src4 + (size_t)si * 32 + lane);
                    float4 c = __ldg(dst4 + (size_t)di * 32 + lane);
                    float4 v;
                    v.x = fabsf(p.x - c.x); v.y = fabsf(p.y - c.y);
                    v.z = fabsf(p.z - c.z); v.w = fabsf(p.w - c.w);
                    *(float4*)(Xb + m * XLD + lane * 4) = tf32x4(v);
                }
                BARR512(1 + b);
            }
            int e = k - 1;
            if (e >= 0 && e < K) {                   // epilogue(e): +A+b1, relu
                int b = e & 1;
                const int ib = e & 3;
                BSYNC512(3 + b);
                float* Xb = X[b];
                #pragma unroll
                for (int it = 0; it < 8; it++) {
                    int m  = pw + it * 8;
                    int si = s_si[ib][m], di = s_di[ib][m];
                    float4 as = __ldg(As4 + (size_t)si * 32 + lane);
                    float4 ad = __ldg(Ad4 + (size_t)di * 32 + lane);
                    float4 v  = *(float4*)(Xb + m * XLD + lane * 4);
                    v.x = fmaxf(v.x + as.x + ad.x + b1r.x, 0.f);
                    v.y = fmaxf(v.y + as.y + ad.y + b1r.y, 0.f);
                    v.z = fmaxf(v.z + as.z + ad.z + b1r.z, 0.f);
                    v.w = fmaxf(v.w + as.w + ad.w + b1r.w, 0.f);
                    *(float4*)(Xb + m * XLD + lane * 4) = tf32x4(v);
                }
                BARR512(5 + b);
            }
            if (k + 2 < K && ptid < BM) {            // stage idx(k+2)
                int tn = (int)blockIdx.x + (k + 2) * G;
                int ee = tn * BM + ptid; if (ee >= n_edges) ee = n_edges - 1;
                const int ib = (k + 2) & 3;
                if (is64) {
                    s_si[ib][ptid] = (int)((const long long*)ei)[ee];
                    s_di[ib][ptid] = (int)((const long long*)ei)[(size_t)n_edges + ee];
                } else {
                    s_si[ib][ptid] = ((const int*)ei)[ee];
                    s_di[ib][ptid] = ((const int*)ei)[(size_t)n_edges + ee];
                }
            }
            if (k + 1 < K && ptid < BM) {            // prefetch tile k+1's rows into L2
                const int ib = (k + 1) & 3;
                size_t si = (size_t)s_si[ib][ptid] * 32;
                size_t di = (size_t)s_di[ib][ptid] * 32;
                #pragma unroll
                for (int jj = 0; jj < 4; jj++) {
                    pf_l2(src4 + si + jj * 8);
                    pf_l2(dst4 + di + jj * 8);
                    pf_l2(As4  + si + jj * 8);
                    pf_l2(Ad4  + di + jj * 8);
                }
            }
        }
    }
}

// ---------------- launch ----------------
extern "C" void kernel_launch(void* const* d_in, const int* in_sizes, int n_in,
                              void* d_out, int out_size)
{
    const float* x_src = (const float*)d_in[0];
    const float* x_dst = (const float*)d_in[1];
    const void*  ei    = d_in[2];
    const float* Wp    = (const float*)d_in[3];
    const float* bp    = (const float*)d_in[4];
    const float* Wc    = (const float*)d_in[5];
    const float* bc    = (const float*)d_in[6];
    const float* W1    = (const float*)d_in[7];
    const float* b1    = (const float*)d_in[8];
    const float* W2    = (const float*)d_in[9];
    const float* b2    = (const float*)d_in[10];

    const int n_nodes = in_sizes[0] / H;
    const int n_edges = in_sizes[2] / 2;

    static int attr_set = 0;
    if (!attr_set) {
        cudaFuncSetAttribute(node_kernel, cudaFuncAttributeMaxDynamicSharedMemorySize, SMEM_BYTES);
        cudaFuncSetAttribute(edge_kernel, cudaFuncAttributeMaxDynamicSharedMemorySize, SMEM_BYTES);
        attr_set = 1;
    }

    detect_idx_kernel<<<1, 64>>>((const int*)ei);

    float* A_src_ptr;  cudaGetSymbolAddress((void**)&A_src_ptr, g_A_src);
    float* A_dst_ptr;  cudaGetSymbolAddress((void**)&A_dst_ptr, g_A_dst);

    const int node_tiles = (n_nodes + BM - 1) / BM;
    const int ngrid = node_tiles < NSM ? node_tiles : NSM;
    node_kernel<<<ngrid, NTHREADS, SMEM_BYTES>>>(
        x_src, x_dst, Wp, bp, Wc, bc, W1, A_src_ptr, A_dst_ptr, n_nodes, node_tiles);

    const int edge_tiles = (n_edges + BM - 1) / BM;
    const int egrid = edge_tiles < NSM ? edge_tiles : NSM;
    edge_kernel<<<egrid, NTHREADS, SMEM_BYTES>>>(
        x_src, x_dst, ei, W1, b1, W2, b2, (float*)d_out, n_edges, edge_tiles);
}